// round 1
// baseline (speedup 1.0000x reference)
#include <cuda_runtime.h>
#include <cstdint>

// ---------------- config ----------------
#define THREADS   256            // 8 warps, warp-per-query within a tile
#define QT        8              // queries per tile (one per warp)
#define QFLOATS   1024           // 128 * 8 floats per query
#define QBYTES    4096           // bytes of h per query
#define STAGE_BYTES (QT * QBYTES)   // 32768
#define STAGES    6
#define SMEM_TOTAL (1024 + STAGES * STAGE_BYTES)  // 197632

using u32 = unsigned int;
using u64 = unsigned long long;

// ---------------- small PTX helpers ----------------
__device__ __forceinline__ u32 s2u(const void* p) {
    u32 a;
    asm("{ .reg .u64 t; cvta.to.shared.u64 t, %1; cvt.u32.u64 %0, t; }"
        : "=r"(a) : "l"(p));
    return a;
}
__device__ __forceinline__ u64 pack2(float x, float y) {
    u64 r; asm("mov.b64 %0, {%1, %2};" : "=l"(r) : "f"(x), "f"(y)); return r;
}
__device__ __forceinline__ float2 unpack2(u64 v) {
    float2 f; asm("mov.b64 {%0, %1}, %2;" : "=f"(f.x), "=f"(f.y) : "l"(v)); return f;
}
// packed fp32 pair fused multiply-add: d = a*b + c (lanewise on {lo,hi})
__device__ __forceinline__ u64 fma2(u64 a, u64 b, u64 c) {
    u64 d; asm("fma.rn.f32x2 %0, %1, %2, %3;" : "=l"(d) : "l"(a), "l"(b), "l"(c));
    return d;
}
__device__ __forceinline__ void mbar_init(u32 m, u32 cnt) {
    asm volatile("mbarrier.init.shared.b64 [%0], %1;" :: "r"(m), "r"(cnt) : "memory");
}
__device__ __forceinline__ void mbar_expect(u32 m, u32 bytes) {
    asm volatile("mbarrier.arrive.expect_tx.shared.b64 _, [%0], %1;"
                 :: "r"(m), "r"(bytes) : "memory");
}
__device__ __forceinline__ void mbar_wait(u32 m, u32 parity) {
    asm volatile(
        "{\n\t"
        ".reg .pred P;\n\t"
        "W1_%=:\n\t"
        "mbarrier.try_wait.parity.acquire.cta.shared::cta.b64 P, [%0], %1, 0x989680;\n\t"
        "@P bra.uni W2_%=;\n\t"
        "bra.uni W1_%=;\n\t"
        "W2_%=:\n\t"
        "}"
        :: "r"(m), "r"(parity) : "memory");
}
// 1D bulk async copy gmem -> smem, completion via mbarrier tx-count
__device__ __forceinline__ void bulk_g2s(u32 dst, const void* src, u32 bytes, u32 mbar) {
    asm volatile(
        "cp.async.bulk.shared::cluster.global.mbarrier::complete_tx::bytes [%0], [%1], %2, [%3];"
        :: "r"(dst), "l"(src), "r"(bytes), "r"(mbar) : "memory");
}

// ---------------- kernel ----------------
// h:    [BQ, 128, 8] f32, contiguous per query (4KB)
// cell: [BQ, 2] f32
// W:    [8, 3, 128] f32  (to_rgb_weight[k][o][c])
// B:    [8, 3] f32       (to_rgb_bias[k][o])
// out:  [BQ, 3] f32
//
// Mapping: warp per query. Lane l of a warp covers, per query, the 8 float4s
// at byte offsets {j*512 + l*16 : j=0..7} within the query's 4KB block.
//   float index f = 128*j + 4*l  =>  c = 16*j + (l>>1),  k in [4*(l&1), 4*(l&1)+4)
// So each lane touches a fixed k-half (4 k's) and 8 c values; its 96 weight
// scalars (48 f32x2 pairs, adjacent in k) live in registers for the whole kernel.
__global__ void __launch_bounds__(THREADS, 1)
gsr_kernel(const float* __restrict__ h, const float* __restrict__ cell,
           const float* __restrict__ W, const float* __restrict__ B,
           float* __restrict__ out, int BQ)
{
    extern __shared__ char smem[];
    const u32 smem_base = s2u(smem);
    const u32 mbar0 = smem_base;           // STAGES mbarriers (8B each) at offset 0
    char* const data = smem + 1024;        // staged h tiles

    const int tid  = threadIdx.x;
    const int warp = tid >> 5;
    const int lane = tid & 31;

    if (tid == 0) {
        #pragma unroll
        for (int s = 0; s < STAGES; s++) mbar_init(mbar0 + 8u * s, 1);
    }
    __syncthreads();

    // ---- per-lane register weights ----
    const int kb = (lane & 1) * 4;   // k base for this lane's half
    const int ch = lane >> 1;        // c offset within each 16-group
    u64 wreg[2][3][8];               // [k-pair within half][o][j]
    #pragma unroll
    for (int kp = 0; kp < 2; kp++)
        #pragma unroll
        for (int o = 0; o < 3; o++)
            #pragma unroll
            for (int j = 0; j < 8; j++) {
                const int k0 = kb + 2 * kp;
                const int c  = 16 * j + ch;
                float wa = W[(k0 * 3 + o) * 128 + c];
                float wb = W[((k0 + 1) * 3 + o) * 128 + c];
                wreg[kp][o][j] = pack2(wa, wb);
            }
    // bias pairs over all 8 k (for the alpha.bias dot, applied once per query)
    u64 bp[4][3];
    #pragma unroll
    for (int kp = 0; kp < 4; kp++)
        #pragma unroll
        for (int o = 0; o < 3; o++)
            bp[kp][o] = pack2(B[(2 * kp) * 3 + o], B[(2 * kp + 1) * 3 + o]);

    const int NT = (BQ + QT - 1) / QT;   // tiles
    const int ct = blockIdx.x;
    const int G  = gridDim.x;

    // ---- pipeline prologue: fill STAGES stages ----
    if (tid == 0) {
        #pragma unroll
        for (int p = 0; p < STAGES; ++p) {
            long long t = (long long)ct + (long long)p * G;
            if (t < NT) {
                int q0  = (int)t * QT;
                int cnt = min(QT, BQ - q0);
                u32 bytes = (u32)cnt * QBYTES;
                u32 dst = smem_base + 1024u + (u32)p * STAGE_BYTES;
                mbar_expect(mbar0 + 8u * p, bytes);
                bulk_g2s(dst, h + (size_t)q0 * QFLOATS, bytes, mbar0 + 8u * p);
            }
        }
    }

    // constants: log(2/256) = -7*ln2 ; (K-1)/log(30)
    const float LOGS0     = -4.8520303f;
    const float TAU_SCALE =  2.0580988f;
    const float NEG_INV2S2 = -0.78125f;   // -1/(2*0.8^2)

    int it = 0;
    for (long long t = ct; t < NT; t += G, ++it) {
        const int s   = it % STAGES;
        const u32 par = (u32)((it / STAGES) & 1);
        const int q0  = (int)t * QT;
        const int q   = q0 + warp;
        const bool active = (q < BQ);

        // --- prefetch cell + compute alpha while TMA lands ---
        float c0 = 0.5f, c1 = 0.5f;
        if (active) { c0 = __ldg(cell + 2 * (size_t)q); c1 = __ldg(cell + 2 * (size_t)q + 1); }
        float gm  = fmaxf(sqrtf(c0 * c1), 1e-10f);
        float tau = (LOGS0 - __logf(gm)) * TAU_SCALE;
        tau = fminf(fmaxf(tau, 0.0f), 7.0f);

        float a[8];
        float ssum = 0.0f;
        #pragma unroll
        for (int k = 0; k < 8; k++) {
            float d = (float)k - tau;
            float v = __expf(d * d * NEG_INV2S2);
            a[k] = v; ssum += v;
        }
        float inv = __fdividef(1.0f, ssum);
        #pragma unroll
        for (int k = 0; k < 8; k++) a[k] *= inv;

        u64 ap[4];
        #pragma unroll
        for (int kp = 0; kp < 4; kp++) ap[kp] = pack2(a[2 * kp], a[2 * kp + 1]);
        const u64 alo = (lane & 1) ? ap[2] : ap[0];
        const u64 ahi = (lane & 1) ? ap[3] : ap[1];

        // --- wait for staged h ---
        mbar_wait(mbar0 + 8u * s, par);

        const char* qs = data + (size_t)s * STAGE_BYTES + (size_t)warp * QBYTES + (size_t)lane * 16;
        u64 acc0[3] = {0ULL, 0ULL, 0ULL};
        u64 acc1[3] = {0ULL, 0ULL, 0ULL};
        #pragma unroll
        for (int j = 0; j < 8; j++) {
            ulonglong2 h2 = *(const ulonglong2*)(qs + j * 512);
            #pragma unroll
            for (int o = 0; o < 3; o++) {
                acc0[o] = fma2(h2.x, wreg[0][o][j], acc0[o]);
                acc1[o] = fma2(h2.y, wreg[1][o][j], acc1[o]);
            }
        }

        float y[3];
        #pragma unroll
        for (int o = 0; o < 3; o++) {
            u64 t2 = fma2(alo, acc0[o], fma2(ahi, acc1[o], 0ULL));
            float2 f = unpack2(t2);
            y[o] = f.x + f.y;
        }
        // bias dot added exactly once per query (lane 0)
        if (lane == 0) {
            #pragma unroll
            for (int o = 0; o < 3; o++) {
                u64 bd = 0ULL;
                #pragma unroll
                for (int kp = 0; kp < 4; kp++) bd = fma2(ap[kp], bp[kp][o], bd);
                float2 f = unpack2(bd);
                y[o] += f.x + f.y;
            }
        }
        // warp reduction over the 32 c/k slices
        #pragma unroll
        for (int o = 0; o < 3; o++) {
            #pragma unroll
            for (int d = 16; d > 0; d >>= 1)
                y[o] += __shfl_xor_sync(0xffffffffu, y[o], d);
        }
        if (active && lane < 3)
            out[3 * (size_t)q + lane] = (lane == 0) ? y[0] : ((lane == 1) ? y[1] : y[2]);

        __syncthreads();   // all warps done reading stage s

        // --- refill stage s with tile t + STAGES*G ---
        if (tid == 0) {
            long long tn = t + (long long)STAGES * G;
            if (tn < NT) {
                int qn  = (int)tn * QT;
                int cnt = min(QT, BQ - qn);
                u32 bytes = (u32)cnt * QBYTES;
                u32 dst = smem_base + 1024u + (u32)s * STAGE_BYTES;
                mbar_expect(mbar0 + 8u * s, bytes);
                bulk_g2s(dst, h + (size_t)qn * QFLOATS, bytes, mbar0 + 8u * s);
            }
        }
    }
}

// ---------------- launch ----------------
extern "C" void kernel_launch(void* const* d_in, const int* in_sizes, int n_in,
                              void* d_out, int out_size)
{
    (void)n_in; (void)out_size;
    const float* h    = (const float*)d_in[0];
    const float* cell = (const float*)d_in[1];
    const float* W    = (const float*)d_in[2];
    const float* B    = (const float*)d_in[3];
    float* out = (float*)d_out;

    const int BQ = in_sizes[1] / 2;

    int dev = 0;
    cudaGetDevice(&dev);
    int sm = 0;
    cudaDeviceGetAttribute(&sm, cudaDevAttrMultiProcessorCount, dev);
    if (sm <= 0) sm = 148;

    cudaFuncSetAttribute(gsr_kernel, cudaFuncAttributeMaxDynamicSharedMemorySize, SMEM_TOTAL);
    gsr_kernel<<<sm, THREADS, SMEM_TOTAL>>>(h, cell, W, B, out, BQ);
}

// round 2
// speedup vs baseline: 1.6443x; 1.6443x over previous
#include <cuda_runtime.h>
#include <cstdint>

// ---------------- config ----------------
#define THREADS   256            // 8 warps
#define WARPS     8
#define QPW       2              // queries per warp per iteration
#define QT        (WARPS * QPW)  // 16 queries per tile
#define QFLOATS   1024           // 128 * 8 floats per query
#define QBYTES    4096
#define STAGE_BYTES (QT * QBYTES)   // 65536
#define STAGES    3
#define SMEM_TOTAL (1024 + STAGES * STAGE_BYTES)  // 197632

using u32 = unsigned int;
using u64 = unsigned long long;

// ---------------- small PTX helpers ----------------
__device__ __forceinline__ u32 s2u(const void* p) {
    u32 a;
    asm("{ .reg .u64 t; cvta.to.shared.u64 t, %1; cvt.u32.u64 %0, t; }"
        : "=r"(a) : "l"(p));
    return a;
}
__device__ __forceinline__ u64 pack2(float x, float y) {
    u64 r; asm("mov.b64 %0, {%1, %2};" : "=l"(r) : "f"(x), "f"(y)); return r;
}
__device__ __forceinline__ float2 unpack2(u64 v) {
    float2 f; asm("mov.b64 {%0, %1}, %2;" : "=f"(f.x), "=f"(f.y) : "l"(v)); return f;
}
__device__ __forceinline__ u64 fma2(u64 a, u64 b, u64 c) {
    u64 d; asm("fma.rn.f32x2 %0, %1, %2, %3;" : "=l"(d) : "l"(a), "l"(b), "l"(c));
    return d;
}
__device__ __forceinline__ void mbar_init(u32 m, u32 cnt) {
    asm volatile("mbarrier.init.shared.b64 [%0], %1;" :: "r"(m), "r"(cnt) : "memory");
}
__device__ __forceinline__ void mbar_expect(u32 m, u32 bytes) {
    asm volatile("mbarrier.arrive.expect_tx.shared.b64 _, [%0], %1;"
                 :: "r"(m), "r"(bytes) : "memory");
}
__device__ __forceinline__ void mbar_wait(u32 m, u32 parity) {
    asm volatile(
        "{\n\t"
        ".reg .pred P;\n\t"
        "W1_%=:\n\t"
        "mbarrier.try_wait.parity.acquire.cta.shared::cta.b64 P, [%0], %1, 0x989680;\n\t"
        "@P bra.uni W2_%=;\n\t"
        "bra.uni W1_%=;\n\t"
        "W2_%=:\n\t"
        "}"
        :: "r"(m), "r"(parity) : "memory");
}
__device__ __forceinline__ void bulk_g2s(u32 dst, const void* src, u32 bytes, u32 mbar) {
    asm volatile(
        "cp.async.bulk.shared::cluster.global.mbarrier::complete_tx::bytes [%0], [%1], %2, [%3];"
        :: "r"(dst), "l"(src), "r"(bytes), "r"(mbar) : "memory");
}

// ---------------- kernel ----------------
// h:    [BQ, 128, 8] f32 (4KB per query, contiguous)
// cell: [BQ, 2] f32
// W:    [8, 3, 128] f32  (to_rgb_weight[k][o][c])
// B:    [8, 3] f32
// out:  [BQ, 3] f32
//
// Warp handles QPW queries per iteration. Lane l covers float4s at byte
// offsets {j*512 + l*16, j=0..7} of each query's 4KB block:
//   c = 16*j + (l>>1),  k in [4*(l&1), 4*(l&1)+4)
// -> 96 weight scalars (48 f32x2 pairs) per lane, register-resident.
__global__ void __launch_bounds__(THREADS, 1)
gsr_kernel(const float* __restrict__ h, const float* __restrict__ cell,
           const float* __restrict__ W, const float* __restrict__ B,
           float* __restrict__ out, int BQ)
{
    extern __shared__ char smem[];
    const u32 smem_base = s2u(smem);
    const u32 mbar0 = smem_base;
    char* const data = smem + 1024;

    const int tid  = threadIdx.x;
    const int warp = tid >> 5;
    const int lane = tid & 31;

    if (tid == 0) {
        #pragma unroll
        for (int s = 0; s < STAGES; s++) mbar_init(mbar0 + 8u * s, 1);
    }
    __syncthreads();

    // ---- per-lane register weights ----
    const int kb = (lane & 1) * 4;
    const int ch = lane >> 1;
    u64 wreg[2][3][8];
    #pragma unroll
    for (int kp = 0; kp < 2; kp++)
        #pragma unroll
        for (int o = 0; o < 3; o++)
            #pragma unroll
            for (int j = 0; j < 8; j++) {
                const int k0 = kb + 2 * kp;
                const int c  = 16 * j + ch;
                wreg[kp][o][j] = pack2(W[(k0 * 3 + o) * 128 + c],
                                       W[((k0 + 1) * 3 + o) * 128 + c]);
            }
    // bias pairs for THIS lane's output channel (lanes 0..2 matter)
    const int o_l = lane < 3 ? lane : 0;
    u64 bpl[4];
    #pragma unroll
    for (int kp = 0; kp < 4; kp++)
        bpl[kp] = pack2(B[(2 * kp) * 3 + o_l], B[(2 * kp + 1) * 3 + o_l]);

    const int NT = (BQ + QT - 1) / QT;
    const int ct = blockIdx.x;
    const int G  = gridDim.x;

    // ---- pipeline prologue: fill STAGES stages ----
    if (tid == 0) {
        #pragma unroll
        for (int p = 0; p < STAGES; ++p) {
            int t = ct + p * G;
            if (t < NT) {
                int q0  = t * QT;
                int cnt = min(QT, BQ - q0);
                u32 bytes = (u32)cnt * QBYTES;
                u32 dst = smem_base + 1024u + (u32)p * STAGE_BYTES;
                mbar_expect(mbar0 + 8u * p, bytes);
                bulk_g2s(dst, h + (size_t)q0 * QFLOATS, bytes, mbar0 + 8u * p);
            }
        }
    }

    // constants
    const float LOGS0     = -4.8520303f;   // log(2/256)
    const float TAU_SCALE =  2.0580988f;   // 7 / log(30)
    // d_k = exp(-(2k-1) * 0.78125) = (e^-0.78125)^(2k-1)
    const float DK[8] = {1.0f, 0.45783335f, 0.09596708f, 0.02011565f,
                         0.00421647f, 0.00088382f, 1.852587e-4f, 3.883240e-5f};

    // ---- preload cell for first tile (one iteration ahead of use) ----
    const float2* cell2 = (const float2*)cell;
    float2 cr[QPW];
    {
        int qb = ct * QT + warp * QPW;
        #pragma unroll
        for (int i = 0; i < QPW; i++)
            cr[i] = (qb + i < BQ) ? __ldg(cell2 + qb + i) : make_float2(1.f, 1.f);
    }

    int it = 0;
    for (int t = ct; t < NT; t += G, ++it) {
        const int s   = it % STAGES;
        const u32 par = (u32)((it / STAGES) & 1);
        const int qb  = t * QT + warp * QPW;

        // ---- alpha for current tile from prefetched cell regs ----
        u64 ap[QPW][4], alo[QPW], ahi[QPW];
        #pragma unroll
        for (int i = 0; i < QPW; i++) {
            float pr  = fmaxf(cr[i].x * cr[i].y, 1e-20f);
            float tau = (LOGS0 - 0.5f * __logf(pr)) * TAU_SCALE;
            tau = fminf(fmaxf(tau, 0.0f), 7.0f);
            // alpha_k  propto  r^k * prod(d) ; one expf instead of eight
            float r = __expf(tau * 1.5625f);
            float pk[8];
            pk[0] = 1.0f;
            float ssum = 1.0f;
            #pragma unroll
            for (int k = 1; k < 8; k++) {
                pk[k] = pk[k - 1] * (r * DK[k]);
                ssum += pk[k];
            }
            float inv = __fdividef(1.0f, ssum);
            float a[8];
            #pragma unroll
            for (int k = 0; k < 8; k++) a[k] = pk[k] * inv;
            #pragma unroll
            for (int kp = 0; kp < 4; kp++) ap[i][kp] = pack2(a[2 * kp], a[2 * kp + 1]);
            alo[i] = (lane & 1) ? ap[i][2] : ap[i][0];
            ahi[i] = (lane & 1) ? ap[i][3] : ap[i][1];
        }

        // ---- prefetch cell for NEXT tile (hides the ~600cyc DRAM latency) ----
        {
            int tn = t + G;
            if (tn < NT) {
                int qn = tn * QT + warp * QPW;
                #pragma unroll
                for (int i = 0; i < QPW; i++)
                    cr[i] = (qn + i < BQ) ? __ldg(cell2 + qn + i) : make_float2(1.f, 1.f);
            }
        }

        // ---- consume staged h ----
        mbar_wait(mbar0 + 8u * s, par);

        const char* sb = data + (size_t)s * STAGE_BYTES;
        float y[QPW][3];
        #pragma unroll
        for (int i = 0; i < QPW; i++) {
            const char* qs = sb + (size_t)(warp * QPW + i) * QBYTES + (size_t)lane * 16;
            u64 acc0[3] = {0ULL, 0ULL, 0ULL};
            u64 acc1[3] = {0ULL, 0ULL, 0ULL};
            #pragma unroll
            for (int j = 0; j < 8; j++) {
                ulonglong2 h2 = *(const ulonglong2*)(qs + j * 512);
                #pragma unroll
                for (int o = 0; o < 3; o++) {
                    acc0[o] = fma2(h2.x, wreg[0][o][j], acc0[o]);
                    acc1[o] = fma2(h2.y, wreg[1][o][j], acc1[o]);
                }
            }
            #pragma unroll
            for (int o = 0; o < 3; o++) {
                u64 t2 = fma2(alo[i], acc0[o], fma2(ahi[i], acc1[o], 0ULL));
                float2 f = unpack2(t2);
                y[i][o] = f.x + f.y;
            }
        }

        // ---- warp reductions: 6 independent 5-step butterfly chains ----
        #pragma unroll
        for (int d = 16; d > 0; d >>= 1) {
            #pragma unroll
            for (int i = 0; i < QPW; i++)
                #pragma unroll
                for (int o = 0; o < 3; o++)
                    y[i][o] += __shfl_xor_sync(0xffffffffu, y[i][o], d);
        }

        // ---- store (+ bias dot, lane==o) ----
        #pragma unroll
        for (int i = 0; i < QPW; i++) {
            int q = qb + i;
            if (q < BQ && lane < 3) {
                u64 bd = 0ULL;
                #pragma unroll
                for (int kp = 0; kp < 4; kp++) bd = fma2(ap[i][kp], bpl[kp], bd);
                float2 f = unpack2(bd);
                float val = ((lane == 0) ? y[i][0] : (lane == 1) ? y[i][1] : y[i][2])
                            + f.x + f.y;
                out[3 * (size_t)q + lane] = val;
            }
        }

        __syncthreads();   // stage s fully consumed by all warps

        // ---- refill stage s ----
        if (tid == 0) {
            int tn = t + STAGES * G;
            if (tn < NT) {
                int qn  = tn * QT;
                int cnt = min(QT, BQ - qn);
                u32 bytes = (u32)cnt * QBYTES;
                u32 dst = smem_base + 1024u + (u32)s * STAGE_BYTES;
                mbar_expect(mbar0 + 8u * s, bytes);
                bulk_g2s(dst, h + (size_t)qn * QFLOATS, bytes, mbar0 + 8u * s);
            }
        }
    }
}

// ---------------- launch ----------------
extern "C" void kernel_launch(void* const* d_in, const int* in_sizes, int n_in,
                              void* d_out, int out_size)
{
    (void)n_in; (void)out_size;
    const float* h    = (const float*)d_in[0];
    const float* cell = (const float*)d_in[1];
    const float* W    = (const float*)d_in[2];
    const float* B    = (const float*)d_in[3];
    float* out = (float*)d_out;

    const int BQ = in_sizes[1] / 2;

    int dev = 0;
    cudaGetDevice(&dev);
    int sm = 0;
    cudaDeviceGetAttribute(&sm, cudaDevAttrMultiProcessorCount, dev);
    if (sm <= 0) sm = 148;

    cudaFuncSetAttribute(gsr_kernel, cudaFuncAttributeMaxDynamicSharedMemorySize, SMEM_TOTAL);
    gsr_kernel<<<sm, THREADS, SMEM_TOTAL>>>(h, cell, W, B, out, BQ);
}